// round 1
// baseline (speedup 1.0000x reference)
#include <cuda_runtime.h>
#include <math.h>

#define NB 8
#define NF 128
#define LATD 256
#define NPIX 4096
#define NCALLS 16
#define FIN 384
#define FO 256
#define KT 197376

#define OFF_WIN  0
#define OFF_BIN  49152
#define OFF_WMID 49280
#define OFF_BMID 65664
#define OFF_WOUT 65792
#define OFF_BOUT 98560
#define OFF_WSH  98816
#define OFF_BSH  197120

// -------- scratch (static device globals; no allocation) --------
__device__ float g_kall[NB * KT];            // 6.3 MB
__device__ float g_p   [NB * FIN * NPIX];    // 50.3 MB
__device__ float g_h1  [NB * NF  * NPIX];    // 16.8 MB
__device__ float g_h2  [NB * NF  * NPIX];    // 16.8 MB
__device__ float g_dn  [NB * FO  * NPIX];    // 33.6 MB

// ======================================================================
// kall = (lat @ hyper_w + hyper_b) * segment_scale
// ======================================================================
__global__ void __launch_bounds__(256) hyper_kernel(
    const float* __restrict__ lat, const float* __restrict__ hw,
    const float* __restrict__ hb, float* __restrict__ kall)
{
    __shared__ float ls[NB * LATD];
    const int tid = threadIdx.x;
    for (int i = tid; i < NB * LATD; i += 256) ls[i] = lat[i];
    __syncthreads();

    const int n = blockIdx.x * 256 + tid;   // grid = 197376/256 = 771 exact
    float acc[NB];
#pragma unroll
    for (int b = 0; b < NB; b++) acc[b] = 0.f;

    for (int k = 0; k < LATD; k++) {
        float w = hw[(size_t)k * KT + n];
#pragma unroll
        for (int b = 0; b < NB; b++) acc[b] = fmaf(ls[b * LATD + k], w, acc[b]);
    }

    float s;
    if      (n < OFF_BIN)  s = 0.05103103630798288f;  // 1/sqrt(384)
    else if (n < OFF_WMID) s = 1.f;
    else if (n < OFF_BMID) s = 0.08838834764831845f;  // 1/sqrt(128)
    else if (n < OFF_WOUT) s = 1.f;
    else if (n < OFF_BOUT) s = 0.08838834764831845f;
    else if (n < OFF_WSH)  s = 1.f;
    else if (n < OFF_BSH)  s = 0.05103103630798288f;
    else                   s = 1.f;

    const float bias = hb[n];
#pragma unroll
    for (int b = 0; b < NB; b++)
        kall[(size_t)b * KT + n] = (acc[b] + bias) * s;
}

// ======================================================================
// build_p: p = instance_norm(concat([x, sobel_x(x), sobel_y(x)]))
// one block per (b, c) 64x64 plane
// ======================================================================
__global__ void __launch_bounds__(256) build_p_kernel(
    const float* __restrict__ X, float* __restrict__ P)
{
    const int c = blockIdx.x;
    const int b = blockIdx.y;
    const int tid = threadIdx.x;

    __shared__ float sp[68 * 68];
    __shared__ float red[8][6];
    __shared__ float stats[6];

    for (int i = tid; i < 68 * 68; i += 256) sp[i] = 0.f;
    __syncthreads();

    const float* Xp = X + ((size_t)b * NF + c) * NPIX;
    for (int i = tid; i < NPIX; i += 256) {
        int y = i >> 6, x = i & 63;
        sp[(y + 2) * 68 + (x + 2)] = Xp[i];
    }
    __syncthreads();

    const float C = 0.70710678118654752f;
    float vx[16], vsx[16], vsy[16];
    float s0 = 0.f, q0 = 0.f, s1 = 0.f, q1 = 0.f, s2 = 0.f, q2 = 0.f;

#pragma unroll
    for (int it = 0; it < 16; it++) {
        int pix = tid + it * 256;
        int y = pix >> 6, x = pix & 63;
        const float* B = &sp[y * 68 + x];   // B[i*68+j] = tap (i,j)

        float xv = B[2 * 68 + 2];
        float sx =
              C    * (B[1*68+4] - B[1*68+0]) + 0.5f * (B[1*68+3] - B[1*68+1])
            +        (B[2*68+4] - B[2*68+0]) + C    * (B[2*68+3] - B[2*68+1])
            + C    * (B[3*68+4] - B[3*68+0]) + 0.5f * (B[3*68+3] - B[3*68+1]);
        float sy =
              C    * (B[4*68+1] - B[0*68+1]) +        (B[4*68+2] - B[0*68+2])
            + C    * (B[4*68+3] - B[0*68+3])
            + 0.5f * (B[3*68+1] - B[1*68+1]) + C    * (B[3*68+2] - B[1*68+2])
            + 0.5f * (B[3*68+3] - B[1*68+3]);

        vx[it] = xv; vsx[it] = sx; vsy[it] = sy;
        s0 += xv; q0 = fmaf(xv, xv, q0);
        s1 += sx; q1 = fmaf(sx, sx, q1);
        s2 += sy; q2 = fmaf(sy, sy, q2);
    }

#pragma unroll
    for (int off = 16; off; off >>= 1) {
        s0 += __shfl_down_sync(0xffffffffu, s0, off);
        q0 += __shfl_down_sync(0xffffffffu, q0, off);
        s1 += __shfl_down_sync(0xffffffffu, s1, off);
        q1 += __shfl_down_sync(0xffffffffu, q1, off);
        s2 += __shfl_down_sync(0xffffffffu, s2, off);
        q2 += __shfl_down_sync(0xffffffffu, q2, off);
    }
    if ((tid & 31) == 0) {
        int w = tid >> 5;
        red[w][0] = s0; red[w][1] = q0; red[w][2] = s1;
        red[w][3] = q1; red[w][4] = s2; red[w][5] = q2;
    }
    __syncthreads();
    if (tid == 0) {
        float S[6] = {0.f, 0.f, 0.f, 0.f, 0.f, 0.f};
        for (int w = 0; w < 8; w++)
            for (int j = 0; j < 6; j++) S[j] += red[w][j];
        const float invN = 1.f / 4096.f;
#pragma unroll
        for (int t3 = 0; t3 < 3; t3++) {
            float mu  = S[2 * t3] * invN;
            float var = fmaxf(S[2 * t3 + 1] * invN - mu * mu, 0.f);
            stats[2 * t3]     = mu;
            stats[2 * t3 + 1] = rsqrtf(var + 1e-5f);
        }
    }
    __syncthreads();

    const float mu0 = stats[0], in0 = stats[1];
    const float mu1 = stats[2], in1 = stats[3];
    const float mu2 = stats[4], in2 = stats[5];

    float* P0 = P + ((size_t)b * FIN + c) * NPIX;
#pragma unroll
    for (int it = 0; it < 16; it++) {
        int pix = tid + it * 256;
        P0[pix]                        = (vx[it]  - mu0) * in0;
        P0[(size_t)NF  * NPIX + pix]   = (vsx[it] - mu1) * in1;
        P0[(size_t)2*NF * NPIX + pix]  = (vsy[it] - mu2) * in2;
    }
}

// ======================================================================
// 128x128 tiled SGEMM: Y[b,m,n] = sum_k W[b,m,k] X[b,k,n]  (+opt 2nd segment)
// BM=BN=128, BK=8, 256 threads, 8x8 per thread
// ======================================================================
__global__ void __launch_bounds__(256) gemm128_kernel(
    const float* __restrict__ kall,
    int w_off1, const float* __restrict__ X1, int K1,
    int w_off2, const float* __restrict__ X2, int K2,
    int b_off1, int b_off2,
    float* __restrict__ Y, int O, int act)
{
    const int b  = blockIdx.z;
    const int n0 = blockIdx.x * 128;
    const int m0 = blockIdx.y * 128;
    const int tid = threadIdx.x;

    __shared__ __align__(16) float Ws[8][132];
    __shared__ __align__(16) float Xs[8][132];

    float acc[8][8];
#pragma unroll
    for (int i = 0; i < 8; i++)
#pragma unroll
        for (int j = 0; j < 8; j++) acc[i][j] = 0.f;

    const int ty = tid >> 4;           // 0..15
    const int tx = tid & 15;           // 0..15
    const int lw_m = tid >> 1;         // 0..127
    const int lw_k = (tid & 1) * 4;    // 0 or 4
    const int lx_k = tid >> 5;         // 0..7
    const int lx_n = (tid & 31) * 4;   // 0..124

#pragma unroll 1
    for (int seg = 0; seg < 2; seg++) {
        const int K = seg ? K2 : K1;
        if (K == 0) continue;
        const float* W = kall + (size_t)b * KT + (seg ? w_off2 : w_off1);
        const float* X = (seg ? X2 : X1) + (size_t)b * K * NPIX;

        for (int k0 = 0; k0 < K; k0 += 8) {
            float4 wv = *reinterpret_cast<const float4*>(&W[(size_t)(m0 + lw_m) * K + k0 + lw_k]);
            float4 xv = *reinterpret_cast<const float4*>(&X[(size_t)(k0 + lx_k) * NPIX + n0 + lx_n]);
            __syncthreads();
            Ws[lw_k + 0][lw_m] = wv.x;
            Ws[lw_k + 1][lw_m] = wv.y;
            Ws[lw_k + 2][lw_m] = wv.z;
            Ws[lw_k + 3][lw_m] = wv.w;
            *reinterpret_cast<float4*>(&Xs[lx_k][lx_n]) = xv;
            __syncthreads();

#pragma unroll
            for (int k = 0; k < 8; k++) {
                float a[8], xr[8];
                *reinterpret_cast<float4*>(&a[0])  = *reinterpret_cast<const float4*>(&Ws[k][ty * 4]);
                *reinterpret_cast<float4*>(&a[4])  = *reinterpret_cast<const float4*>(&Ws[k][ty * 4 + 64]);
                *reinterpret_cast<float4*>(&xr[0]) = *reinterpret_cast<const float4*>(&Xs[k][tx * 4]);
                *reinterpret_cast<float4*>(&xr[4]) = *reinterpret_cast<const float4*>(&Xs[k][tx * 4 + 64]);
#pragma unroll
                for (int i = 0; i < 8; i++)
#pragma unroll
                    for (int j = 0; j < 8; j++)
                        acc[i][j] = fmaf(a[i], xr[j], acc[i][j]);
            }
        }
    }

    const float* bs1 = kall + (size_t)b * KT + b_off1;
    const float* bs2 = (b_off2 >= 0) ? (kall + (size_t)b * KT + b_off2) : nullptr;
    float* Yb = Y + (size_t)b * O * NPIX;

#pragma unroll
    for (int gi = 0; gi < 2; gi++)
#pragma unroll
        for (int ii = 0; ii < 4; ii++) {
            const int m = m0 + gi * 64 + ty * 4 + ii;
            float bv = bs1[m];
            if (bs2) bv += bs2[m];
#pragma unroll
            for (int gj = 0; gj < 2; gj++) {
                float4 o4;
                o4.x = acc[gi * 4 + ii][gj * 4 + 0] + bv;
                o4.y = acc[gi * 4 + ii][gj * 4 + 1] + bv;
                o4.z = acc[gi * 4 + ii][gj * 4 + 2] + bv;
                o4.w = acc[gi * 4 + ii][gj * 4 + 3] + bv;
                if (act) {
                    o4.x = fmaxf(o4.x, 0.f); o4.y = fmaxf(o4.y, 0.f);
                    o4.z = fmaxf(o4.z, 0.f); o4.w = fmaxf(o4.w, 0.f);
                }
                *reinterpret_cast<float4*>(&Yb[(size_t)m * NPIX + n0 + gj * 64 + tx * 4]) = o4;
            }
        }
}

// ======================================================================
// gated state update: x_new = x + leak * val * sigmoid(gate)
// ======================================================================
__global__ void __launch_bounds__(256) update_kernel(
    const float* __restrict__ dn, const float* __restrict__ xin,
    float* __restrict__ xout, const float* __restrict__ leakp)
{
    const int i = blockIdx.x * 256 + threadIdx.x;      // float4 index
    const float leak = fminf(fmaxf(leakp[0], 0.001f), 1000.f);
    const int b = i / 131072;                           // 128*4096/4
    const int r = i - b * 131072;

    const float4 v = reinterpret_cast<const float4*>(dn)[(size_t)b * 262144 + r];
    const float4 g = reinterpret_cast<const float4*>(dn)[(size_t)b * 262144 + 131072 + r];
    const float4 x = reinterpret_cast<const float4*>(xin)[i];
    float4 o;
    o.x = x.x + leak * v.x / (1.f + expf(-g.x));
    o.y = x.y + leak * v.y / (1.f + expf(-g.y));
    o.z = x.z + leak * v.z / (1.f + expf(-g.z));
    o.w = x.w + leak * v.w / (1.f + expf(-g.w));
    reinterpret_cast<float4*>(xout)[i] = o;
}

// ======================================================================
// 3x3 conv, 128->128 channels.  32 o-channels x (4 rows x 64 cols) per block.
// act=1: relu.  X0 != null: residual add.
// ======================================================================
__global__ void __launch_bounds__(256) conv3x3_kernel(
    const float* __restrict__ X, const float* __restrict__ W,
    const float* __restrict__ bias, const float* __restrict__ X0,
    float* __restrict__ Y, int act)
{
    const int b  = blockIdx.z;
    const int o0 = blockIdx.y * 32;
    const int y0 = blockIdx.x * 4;
    const int tid = threadIdx.x;
    const int og = tid >> 5;           // 0..7
    const int pg = tid & 31;
    const int r  = pg >> 3;            // 0..3
    const int xb = (pg & 7) * 8;       // 0..56

    __shared__ float sIn[6][66];
    __shared__ float sW[32 * 9];

    float acc[4][8];
#pragma unroll
    for (int oi = 0; oi < 4; oi++)
#pragma unroll
        for (int px = 0; px < 8; px++) acc[oi][px] = 0.f;

    const float* Xb = X + (size_t)b * NF * NPIX;

    for (int ci = 0; ci < NF; ci++) {
        __syncthreads();
        for (int i = tid; i < 6 * 66; i += 256) {
            int ry = i / 66, cx = i - ry * 66;
            int gy = y0 - 1 + ry, gx = cx - 1;
            float v = 0.f;
            if ((unsigned)gy < 64u && (unsigned)gx < 64u)
                v = Xb[(size_t)ci * NPIX + gy * 64 + gx];
            sIn[ry][cx] = v;
        }
        for (int i = tid; i < 288; i += 256) {
            int oi = i / 9, j = i - oi * 9;
            sW[i] = W[(size_t)(o0 + oi) * 1152 + ci * 9 + j];
        }
        __syncthreads();

        float in[3][10];
#pragma unroll
        for (int dy = 0; dy < 3; dy++)
#pragma unroll
            for (int dx = 0; dx < 10; dx++)
                in[dy][dx] = sIn[r + dy][xb + dx];

#pragma unroll
        for (int oi = 0; oi < 4; oi++) {
            float wr[9];
#pragma unroll
            for (int j = 0; j < 9; j++) wr[j] = sW[(og * 4 + oi) * 9 + j];
#pragma unroll
            for (int px = 0; px < 8; px++) {
                float s = acc[oi][px];
#pragma unroll
                for (int dy = 0; dy < 3; dy++)
#pragma unroll
                    for (int dx = 0; dx < 3; dx++)
                        s = fmaf(in[dy][px + dx], wr[dy * 3 + dx], s);
                acc[oi][px] = s;
            }
        }
    }

#pragma unroll
    for (int oi = 0; oi < 4; oi++) {
        const int o = o0 + og * 4 + oi;
        const float bv = bias[o];
#pragma unroll
        for (int px = 0; px < 8; px++) {
            size_t idx = ((size_t)b * NF + o) * NPIX + (size_t)(y0 + r) * 64 + xb + px;
            float v = acc[oi][px] + bv;
            if (X0) v += X0[idx];
            if (act) v = fmaxf(v, 0.f);
            Y[idx] = v;
        }
    }
}

// ======================================================================
// final 128->3 conv + clip; writes out_raw and out_img
// ======================================================================
__global__ void __launch_bounds__(256) conv_img_kernel(
    const float* __restrict__ X, const float* __restrict__ W,
    const float* __restrict__ bias,
    float* __restrict__ out_img, float* __restrict__ out_raw)
{
    const int b  = blockIdx.y;
    const int y0 = blockIdx.x * 4;
    const int tid = threadIdx.x;
    const int r = tid >> 6;
    const int x = tid & 63;

    __shared__ float sW[3 * 1152];
    __shared__ float sIn[6][66];

    for (int i = tid; i < 3 * 1152; i += 256) sW[i] = W[i];

    float acc[3] = {0.f, 0.f, 0.f};
    const float* Xb = X + (size_t)b * NF * NPIX;

    for (int ci = 0; ci < NF; ci++) {
        __syncthreads();
        for (int i = tid; i < 6 * 66; i += 256) {
            int ry = i / 66, cx = i - ry * 66;
            int gy = y0 - 1 + ry, gx = cx - 1;
            float v = 0.f;
            if ((unsigned)gy < 64u && (unsigned)gx < 64u)
                v = Xb[(size_t)ci * NPIX + gy * 64 + gx];
            sIn[ry][cx] = v;
        }
        __syncthreads();

        float in[9];
#pragma unroll
        for (int dy = 0; dy < 3; dy++)
#pragma unroll
            for (int dx = 0; dx < 3; dx++)
                in[dy * 3 + dx] = sIn[r + dy][x + dx];

#pragma unroll
        for (int o = 0; o < 3; o++) {
#pragma unroll
            for (int j = 0; j < 9; j++)
                acc[o] = fmaf(in[j], sW[o * 1152 + ci * 9 + j], acc[o]);
        }
    }

#pragma unroll
    for (int o = 0; o < 3; o++) {
        float v = acc[o] + bias[o];
        size_t idx = ((size_t)b * 3 + o) * NPIX + (size_t)(y0 + r) * 64 + x;
        out_raw[idx] = v;
        out_img[idx] = fminf(fmaxf(v, -1.f), 1.f);
    }
}

// ======================================================================
// launch
// ======================================================================
extern "C" void kernel_launch(void* const* d_in, const int* in_sizes, int n_in,
                              void* d_out, int out_size)
{
    const float* lat  = (const float*)d_in[0];
    const float* ca   = (const float*)d_in[1];
    const float* leak = (const float*)d_in[2];
    const float* hw   = (const float*)d_in[3];
    const float* hb   = (const float*)d_in[4];
    const float* rw1  = (const float*)d_in[5];
    const float* rb1  = (const float*)d_in[6];
    const float* rw2  = (const float*)d_in[7];
    const float* rb2  = (const float*)d_in[8];
    const float* iw   = (const float*)d_in[9];
    const float* ib   = (const float*)d_in[10];

    float* out = (float*)d_out;
    float* out_img = out;                                  // (8,3,64,64)
    float* embs    = out + 98304;                          // (17,8,128,64,64)
    float* out_raw = out + 98304 + (size_t)17 * 4194304;   // (8,3,64,64)

    float *kall, *p, *h1, *h2, *dn;
    cudaGetSymbolAddress((void**)&kall, g_kall);
    cudaGetSymbolAddress((void**)&p,    g_p);
    cudaGetSymbolAddress((void**)&h1,   g_h1);
    cudaGetSymbolAddress((void**)&h2,   g_h2);
    cudaGetSymbolAddress((void**)&dn,   g_dn);

    hyper_kernel<<<KT / 256, 256>>>(lat, hw, hb, kall);
    cudaMemcpyAsync(embs, ca, (size_t)4194304 * sizeof(float),
                    cudaMemcpyDeviceToDevice);

    for (int t = 0; t < NCALLS; t++) {
        float* x  = embs + (size_t)t * 4194304;
        float* xn = x + 4194304;

        build_p_kernel<<<dim3(NF, NB), 256>>>(x, p);

        // h1 = relu(W_in @ p + b_in)
        gemm128_kernel<<<dim3(32, 1, NB), 256>>>(
            kall, OFF_WIN, p, FIN, 0, nullptr, 0, OFF_BIN, -1, h1, NF, 1);
        // h2 = relu(W_mid @ h1 + b_mid)
        gemm128_kernel<<<dim3(32, 1, NB), 256>>>(
            kall, OFF_WMID, h1, NF, 0, nullptr, 0, OFF_BMID, -1, h2, NF, 1);
        // dn = W_out @ h2 + W_sh @ p + b_out + b_sh
        gemm128_kernel<<<dim3(32, 2, NB), 256>>>(
            kall, OFF_WOUT, h2, NF, OFF_WSH, p, FIN, OFF_BOUT, OFF_BSH, dn, FO, 0);

        update_kernel<<<4096, 256>>>(dn, x, xn, leak);
    }

    float* xf = embs + (size_t)NCALLS * 4194304;
    // h = relu(conv3x3(xf, res_w1) + res_b1)
    conv3x3_kernel<<<dim3(16, 4, NB), 256>>>(xf, rw1, rb1, nullptr, h1, 1);
    // y = xf + conv3x3(h, res_w2) + res_b2
    conv3x3_kernel<<<dim3(16, 4, NB), 256>>>(h1, rw2, rb2, xf, h2, 0);
    // out_raw / out_img
    conv_img_kernel<<<dim3(16, NB), 256>>>(h2, iw, ib, out_img, out_raw);
}